// round 9
// baseline (speedup 1.0000x reference)
#include <cuda_runtime.h>
#include <cuda_fp16.h>
#include <stdint.h>

// Problem constants
#define R_I     512
#define R_O     32
#define R_CHI   16                 // inputs per chunk
#define R_CHK   128                // k per chunk (16*8, j=0 folded to bias)
#define R_NCH   32
#define R_ROWS  64                 // batch rows per CTA
#define R_THR   128                // 4 warps, each owns 16 rows of the MMA

// smem layout (bytes): W double buffer then basis double buffer
#define WPAD    136                // halves per W row (o): 128 + 8 pad
#define BPAD    72                 // halves per basis row (k): 64 + 8 pad
#define SM_W0   0
#define SM_W1   (R_O * WPAD * 2)                   // 8704
#define SM_B0   (2 * R_O * WPAD * 2)               // 17408
#define SM_B1   (SM_B0 + R_CHK * BPAD * 2)         // 35840
#define SM_TOT  (SM_B1 + R_CHK * BPAD * 2)         // 54272

// Repacked fp16 weights (j=1..8): g_W2[c][o][kl], kl = ip*8 + (j-1)
__device__ __half g_W2[R_NCH * R_O * R_CHK];
__device__ float  g_bias[R_O];

__global__ void repack_kernel(const float* __restrict__ w) {
    int idx = blockIdx.x * blockDim.x + threadIdx.x;
    if (idx >= R_NCH * R_O * R_CHK) return;
    int kl = idx & 127;
    int o  = (idx >> 7) & 31;
    int c  = idx >> 12;
    int i  = c * R_CHI + (kl >> 3);
    int j  = (kl & 7) + 1;
    g_W2[idx] = __float2half(w[(i * R_O + o) * 9 + j]);
}

// Parallel bias: 256 threads, smem reduce
__global__ void bias_kernel(const float* __restrict__ w) {
    __shared__ float red[256];
    int t = threadIdx.x;
    int o = t & 31, g = t >> 5;
    float s = 0.0f;
#pragma unroll 8
    for (int i = g; i < R_I; i += 8) s += w[(i * R_O + o) * 9];
    red[t] = s;
    __syncthreads();
    if (t < 32) {
        float tot = 0.0f;
#pragma unroll
        for (int q = 0; q < 8; ++q) tot += red[q * 32 + t];
        g_bias[t] = tot;
    }
}

// ---------------- primitives ----------------
__device__ __forceinline__ uint32_t smem_u32(const void* p) {
    uint32_t a;
    asm("{ .reg .u64 t; cvta.to.shared.u64 t, %1; cvt.u32.u64 %0, t; }" : "=r"(a) : "l"(p));
    return a;
}
__device__ __forceinline__ void ldm_x4(uint32_t (&r)[4], uint32_t addr) {
    asm volatile("ldmatrix.sync.aligned.m8n8.x4.shared.b16 {%0,%1,%2,%3}, [%4];"
                 : "=r"(r[0]), "=r"(r[1]), "=r"(r[2]), "=r"(r[3]) : "r"(addr));
}
__device__ __forceinline__ void ldm_x4_t(uint32_t (&r)[4], uint32_t addr) {
    asm volatile("ldmatrix.sync.aligned.m8n8.x4.trans.shared.b16 {%0,%1,%2,%3}, [%4];"
                 : "=r"(r[0]), "=r"(r[1]), "=r"(r[2]), "=r"(r[3]) : "r"(addr));
}
__device__ __forceinline__ void mma16816(float (&d)[4], const uint32_t (&a)[4],
                                         uint32_t b0, uint32_t b1) {
    asm volatile(
        "mma.sync.aligned.m16n8k16.row.col.f32.f16.f16.f32 "
        "{%0,%1,%2,%3}, {%4,%5,%6,%7}, {%8,%9}, {%0,%1,%2,%3};"
        : "+f"(d[0]), "+f"(d[1]), "+f"(d[2]), "+f"(d[3])
        : "r"(a[0]), "r"(a[1]), "r"(a[2]), "r"(a[3]), "r"(b0), "r"(b1));
}
__device__ __forceinline__ uint32_t pack2(float a, float b) {
    __half2 h = __floats2half2_rn(a, b);
    return *reinterpret_cast<uint32_t*>(&h);
}
__device__ __forceinline__ float ftanh(float x) {
    float p;
    asm("ex2.approx.f32 %0, %1;" : "=f"(p) : "f"(x * 2.8853900817779268f));
    float r;
    asm("rcp.approx.f32 %0, %1;" : "=f"(r) : "f"(p + 1.0f));
    return fmaf(-2.0f, r, 1.0f);
}

__global__ __launch_bounds__(R_THR)
void cheby_mma_kernel(const float* __restrict__ x, float* __restrict__ out) {
    extern __shared__ char smem[];
    const uint32_t sb = smem_u32(smem);
    __half* smh = reinterpret_cast<__half*>(smem);

    const int t    = threadIdx.x;
    const int lane = t & 31;
    const int w    = t >> 5;            // warp id: MMA rows [16w, 16w+16)
    const int b0   = blockIdx.x * R_ROWS;

    // gen mapping: thread owns row-pair (2rp, 2rp+1), inputs [4ig, 4ig+4) of chunk
    const int rp = t & 31;
    const int ig = t >> 5;

    // ldmatrix lane address components
    const int g = lane >> 3, l = lane & 7;
    const int oRow = (g & 1) * 8 + l;
    const int kHlf = (g >> 1) * 8;
    const uint32_t wOff = (uint32_t)(oRow * WPAD + kHlf) * 2u;
    const int kOff = (g >> 1) * 8 + l;
    const int mOff = (g & 1) * 8;
    const uint32_t bOff = (uint32_t)(kOff * BPAD + w * 16 + mOff) * 2u;

    float acc[2][2][4];
#pragma unroll
    for (int ot = 0; ot < 2; ++ot)
#pragma unroll
        for (int rt = 0; rt < 2; ++rt)
#pragma unroll
            for (int q = 0; q < 4; ++q) acc[ot][rt][q] = 0.0f;

    const float* xr0 = x + (size_t)(b0 + 2 * rp) * R_I + ig * 4;   // row even
    const float* xr1 = xr0 + R_I;                                   // row odd

    // ---- W stage helper (inline): chunk -> smem buffer ----
    auto stageW = [&](int c, uint32_t sWb) {
        const __half* wp = g_W2 + (size_t)c * (R_O * R_CHK);
#pragma unroll
        for (int q = 0; q < 4; ++q) {
            int flat = q * 128 + t;            // 0..511
            int o = flat >> 4, seg = flat & 15;
            uint4 v = *reinterpret_cast<const uint4*>(wp + o * R_CHK + seg * 8);
            *reinterpret_cast<uint4*>(smh + (sWb >> 1) + o * WPAD + seg * 8) = v;
        }
    };
    // ---- basis gen helper: 4 inputs x 2 rows from regs -> smem buffer ----
    auto genB = [&](float4 va, float4 vb, uint32_t sBb) {
        float xa[4] = {va.x, va.y, va.z, va.w};
        float xb[4] = {vb.x, vb.y, vb.z, vb.w};
#pragma unroll
        for (int p = 0; p < 4; ++p) {
            float t0 = ftanh(xa[p]);
            float t1 = ftanh(xb[p]);
            float x20 = t0 + t0, x21 = t1 + t1;
            float a0 = 1.0f, b0v = 1.0f;        // U0 folded into bias
            float a1 = x20, b1v = x21;          // U1
            uint32_t ad = sb + sBb + (uint32_t)(((ig * 4 + p) * 8) * BPAD + 2 * rp) * 2u;
#pragma unroll
            for (int j = 1; j <= 8; ++j) {
                asm volatile("st.shared.b32 [%0], %1;" :: "r"(ad), "r"(pack2(a1, b1v)));
                ad += BPAD * 2;
                if (j < 8) {
                    float a2 = fmaf(x20, a1, -a0);
                    float b2 = fmaf(x21, b1v, -b0v);
                    a0 = a1; a1 = a2; b0v = b1v; b1v = b2;
                }
            }
        }
    };

    // ---- prologue: chunk 0 into buffer 0; prefetch x(1) ----
    float4 xa = *reinterpret_cast<const float4*>(xr0);
    float4 xb = *reinterpret_cast<const float4*>(xr1);
    stageW(0, SM_W0);
    genB(xa, xb, SM_B0);
    xa = *reinterpret_cast<const float4*>(xr0 + R_CHI);
    xb = *reinterpret_cast<const float4*>(xr1 + R_CHI);
    __syncthreads();

    // ---- main loop: ONE sync per chunk; gen(c+1) overlaps MMA(c) ----
    for (int c = 0; c < R_NCH; ++c) {
        const int buf = c & 1;

        if (c + 1 < R_NCH) {
            float4 ta = xa, tb = xb;
            if (c + 2 < R_NCH) {     // prefetch x(c+2); consumed next iteration
                xa = *reinterpret_cast<const float4*>(xr0 + (c + 2) * R_CHI);
                xb = *reinterpret_cast<const float4*>(xr1 + (c + 2) * R_CHI);
            }
            stageW(c + 1, buf ? SM_W0 : SM_W1);
            genB(ta, tb, buf ? SM_B0 : SM_B1);
        }

        // ---- MMA(c): 8 k16-steps on this warp's 16 rows ----
        uint32_t wAddr = sb + (buf ? SM_W1 : SM_W0) + wOff;
        uint32_t bAddr = sb + (buf ? SM_B1 : SM_B0) + bOff;
#pragma unroll
        for (int ks = 0; ks < 8; ++ks) {
            uint32_t aW0[4], aW1[4], bb[4];
            ldm_x4(aW0, wAddr);                       // o 0..15
            ldm_x4(aW1, wAddr + 16u * WPAD * 2u);     // o 16..31
            ldm_x4_t(bb, bAddr);                      // 16 rows x 16 k
            mma16816(acc[0][0], aW0, bb[0], bb[2]);   // rows +0..7
            mma16816(acc[1][0], aW1, bb[0], bb[2]);
            mma16816(acc[0][1], aW0, bb[1], bb[3]);   // rows +8..15
            mma16816(acc[1][1], aW1, bb[1], bb[3]);
            wAddr += 32u;                  // +16 halves along k
            bAddr += 16u * BPAD * 2u;      // +16 k-rows
        }
        __syncthreads();
    }

    // ---- epilogue: add bias, store ----
    const int qr = lane >> 2;
    const int qc = (lane & 3) * 2;
    float bo[2][2];
#pragma unroll
    for (int ot = 0; ot < 2; ++ot) {
        bo[ot][0] = g_bias[ot * 16 + qr];
        bo[ot][1] = g_bias[ot * 16 + qr + 8];
    }
#pragma unroll
    for (int rt = 0; rt < 2; ++rt) {
        int r = b0 + 16 * w + 8 * rt + qc;
        float* po0 = out + (size_t)r * R_O;
        float* po1 = out + (size_t)(r + 1) * R_O;
#pragma unroll
        for (int ot = 0; ot < 2; ++ot) {
            int o = ot * 16 + qr;
            po0[o]     = acc[ot][rt][0] + bo[ot][0];
            po1[o]     = acc[ot][rt][1] + bo[ot][0];
            po0[o + 8] = acc[ot][rt][2] + bo[ot][1];
            po1[o + 8] = acc[ot][rt][3] + bo[ot][1];
        }
    }
}

extern "C" void kernel_launch(void* const* d_in, const int* in_sizes, int n_in,
                              void* d_out, int out_size) {
    const float* x  = (const float*)d_in[0];     // [65536, 512] f32
    const float* wc = (const float*)d_in[1];     // [512, 32, 9] f32
    float* out = (float*)d_out;                  // [65536, 32] f32

    int Brows = in_sizes[0] / R_I;

    static int smem_set = 0;
    if (!smem_set) {
        cudaFuncSetAttribute(cheby_mma_kernel,
                             cudaFuncAttributeMaxDynamicSharedMemorySize, SM_TOT);
        smem_set = 1;
    }

    int wtot = R_NCH * R_O * R_CHK;              // 131072
    repack_kernel<<<(wtot + 255) / 256, 256>>>(wc);
    bias_kernel<<<1, 256>>>(wc);

    cheby_mma_kernel<<<Brows / R_ROWS, R_THR, SM_TOT>>>(x, out);
}

// round 10
// speedup vs baseline: 1.2526x; 1.2526x over previous
#include <cuda_runtime.h>
#include <cuda_fp16.h>
#include <stdint.h>
#include <math.h>

// Problem constants (R4 layout exactly; only the warp organization changed)
#define P_I     512
#define P_O     32
#define P_J     9
#define P_CHI   16                 // inputs per k-chunk
#define P_CHK   144                // dense k per chunk (16*9)
#define P_NCH   32                 // 512/16
#define P_ROWS  128                // batch rows per CTA
#define P_THR   256                // 8 warps: (w&3)=row group, (w>>2)=o half

// smem layout (halves): W [32][152] then basisT [144][136]
#define WPAD    152
#define BPAD    136
#define SM_W    0
#define SM_B    (P_O * WPAD * 2)                   // 9728 bytes
#define SM_TOT  (SM_B + P_CHK * BPAD * 2)          // 48896 bytes (<48KB)

// Repacked fp16 weights, dense-k chunk-major: g_W2[c][o][kl], kl=0..143
__device__ __half g_W2[P_NCH * P_O * P_CHK];

__global__ void repack_kernel(const float* __restrict__ w) {
    int idx = blockIdx.x * blockDim.x + threadIdx.x;
    if (idx >= P_NCH * P_O * P_CHK) return;
    int kl = idx % P_CHK;
    int o  = (idx / P_CHK) % P_O;
    int c  = idx / (P_CHK * P_O);
    int k  = c * P_CHK + kl;
    int i  = k / P_J;
    int j  = k % P_J;
    g_W2[idx] = __float2half(w[(i * P_O + o) * P_J + j]);
}

// ---------------- warp-level MMA primitives ----------------
__device__ __forceinline__ uint32_t smem_u32(const void* p) {
    uint32_t a;
    asm("{ .reg .u64 t; cvta.to.shared.u64 t, %1; cvt.u32.u64 %0, t; }" : "=r"(a) : "l"(p));
    return a;
}
__device__ __forceinline__ void ldm_x4(uint32_t (&r)[4], uint32_t addr) {
    asm volatile("ldmatrix.sync.aligned.m8n8.x4.shared.b16 {%0,%1,%2,%3}, [%4];"
                 : "=r"(r[0]), "=r"(r[1]), "=r"(r[2]), "=r"(r[3]) : "r"(addr));
}
__device__ __forceinline__ void ldm_x4_t(uint32_t (&r)[4], uint32_t addr) {
    asm volatile("ldmatrix.sync.aligned.m8n8.x4.trans.shared.b16 {%0,%1,%2,%3}, [%4];"
                 : "=r"(r[0]), "=r"(r[1]), "=r"(r[2]), "=r"(r[3]) : "r"(addr));
}
__device__ __forceinline__ void mma16816(float (&d)[4], const uint32_t (&a)[4],
                                         uint32_t b0, uint32_t b1) {
    asm volatile(
        "mma.sync.aligned.m16n8k16.row.col.f32.f16.f16.f32 "
        "{%0,%1,%2,%3}, {%4,%5,%6,%7}, {%8,%9}, {%0,%1,%2,%3};"
        : "+f"(d[0]), "+f"(d[1]), "+f"(d[2]), "+f"(d[3])
        : "r"(a[0]), "r"(a[1]), "r"(a[2]), "r"(a[3]), "r"(b0), "r"(b1));
}
__device__ __forceinline__ uint32_t pack2(float a, float b) {
    __half2 h = __floats2half2_rn(a, b);
    return *reinterpret_cast<uint32_t*>(&h);
}

__global__ __launch_bounds__(P_THR)
void cheby_mma_kernel(const float* __restrict__ x, float* __restrict__ out) {
    extern __shared__ char smem[];
    const uint32_t sW = smem_u32(smem) + SM_W;
    const uint32_t sB = smem_u32(smem) + SM_B;
    __half* smW = reinterpret_cast<__half*>(smem + SM_W);

    const int t    = threadIdx.x;
    const int lane = t & 31;
    const int w    = t >> 5;            // 0..7
    const int wm   = w & 3;             // row group: rows [32wm, 32wm+32)
    const int oh   = w >> 2;            // o half: o [16oh, 16oh+16)
    const int b0   = blockIdx.x * P_ROWS;

    // gen mapping (R4, threads 0-127 only): row-pair (2rp, 2rp+1), inputs [8ig, 8ig+8)
    const int rp = t & 63;
    const int ig = (t >> 6) & 1;

    // ldmatrix per-lane address components
    const int g = lane >> 3, l = lane & 7;
    const int oRow = (g & 1) * 8 + l;
    const int kHlf = (g >> 1) * 8;
    const uint32_t wAddrBase = sW + (uint32_t)((oh * 16 + oRow) * WPAD + kHlf) * 2u;
    const int kOff = (g >> 1) * 8 + l;
    const int mOff = (g & 1) * 8;
    const uint32_t bAddrBase = sB + (uint32_t)(kOff * BPAD + wm * 32 + mOff) * 2u;

    float acc[4][4];
#pragma unroll
    for (int rt = 0; rt < 4; ++rt)
#pragma unroll
        for (int q = 0; q < 4; ++q) acc[rt][q] = 0.0f;

    for (int c = 0; c < P_NCH; ++c) {
        if (c) __syncthreads();        // mma of chunk c-1 done reading smem

        // ---- load W chunk (9216 B = 576 uint4) to smem: 256 threads ----
        {
            const __half* wp = g_W2 + (size_t)c * (P_O * P_CHK);
#pragma unroll
            for (int q = 0; q < 3; ++q) {
                int idx = t + P_THR * q;
                if (idx < (P_O * P_CHK) / 8) {
                    int o = idx / 18, s = idx % 18;  // 18 x 8 halves per o-row
                    uint4 v = *reinterpret_cast<const uint4*>(wp + o * P_CHK + s * 8);
                    *reinterpret_cast<uint4*>(smW + o * WPAD + s * 8) = v;
                }
            }
        }

        // ---- generate basis tile (threads 0-127, exactly as R4) ----
        if (t < 128) {
            const float* xp = x + (size_t)(b0 + 2 * rp) * P_I + c * P_CHI + ig * 8;
            float xr0[8], xr1[8];
            *reinterpret_cast<float4*>(&xr0[0]) = *reinterpret_cast<const float4*>(xp);
            *reinterpret_cast<float4*>(&xr0[4]) = *reinterpret_cast<const float4*>(xp + 4);
            *reinterpret_cast<float4*>(&xr1[0]) = *reinterpret_cast<const float4*>(xp + P_I);
            *reinterpret_cast<float4*>(&xr1[4]) = *reinterpret_cast<const float4*>(xp + P_I + 4);
#pragma unroll
            for (int p = 0; p < 8; ++p) {
                float t0 = tanhf(xr0[p]);
                float t1 = tanhf(xr1[p]);
                float x20 = t0 + t0, x21 = t1 + t1;
                uint32_t base = sB + (uint32_t)(((ig * 8 + p) * P_J) * BPAD + 2 * rp) * 2u;
                float a0 = 1.0f, b0v = 1.0f;      // U0
                float a1 = x20, b1v = x21;        // U1
                asm volatile("st.shared.b32 [%0], %1;" :: "r"(base), "r"(pack2(a0, b0v)));
                asm volatile("st.shared.b32 [%0], %1;" :: "r"(base + BPAD * 2), "r"(pack2(a1, b1v)));
#pragma unroll
                for (int j = 2; j <= 8; ++j) {
                    float a2 = fmaf(x20, a1, -a0);
                    float b2 = fmaf(x21, b1v, -b0v);
                    asm volatile("st.shared.b32 [%0], %1;"
                                 :: "r"(base + (uint32_t)(j * BPAD * 2)), "r"(pack2(a2, b2)));
                    a0 = a1; a1 = a2; b0v = b1v; b1v = b2;
                }
            }
        }
        __syncthreads();

        // ---- MMA: 9 k16-steps; this warp: 16 o x 32 rows ----
        uint32_t wAddr = wAddrBase;
        uint32_t bAddr = bAddrBase;
#pragma unroll
        for (int ks = 0; ks < 9; ++ks) {
            uint32_t aW[4], bb0[4], bb1[4];
            ldm_x4(aW, wAddr);                        // this warp's 16 o-rows
            ldm_x4_t(bb0, bAddr);                     // rows m0..m0+15
            ldm_x4_t(bb1, bAddr + 32u);               // rows m0+16..m0+31
            mma16816(acc[0], aW, bb0[0], bb0[2]);
            mma16816(acc[1], aW, bb0[1], bb0[3]);
            mma16816(acc[2], aW, bb1[0], bb1[2]);
            mma16816(acc[3], aW, bb1[1], bb1[3]);
            wAddr += 32u;                  // +16 halves along k
            bAddr += 16u * BPAD * 2u;      // +16 k-rows
        }
    }

    // ---- epilogue: C fragment -> gmem (each warp its 32-row x 16-o quarter) ----
    const int qr = lane >> 2;            // m-row within tile (o low 3 bits)
    const int qc = (lane & 3) * 2;       // n-col within tile (batch row pair)
    const int ob = oh * 16 + qr;
#pragma unroll
    for (int rt = 0; rt < 4; ++rt) {
        int r = b0 + 32 * wm + 8 * rt + qc;
        float* po0 = out + (size_t)r * P_O;
        float* po1 = out + (size_t)(r + 1) * P_O;
        po0[ob]     = acc[rt][0];
        po1[ob]     = acc[rt][1];
        po0[ob + 8] = acc[rt][2];
        po1[ob + 8] = acc[rt][3];
    }
}

extern "C" void kernel_launch(void* const* d_in, const int* in_sizes, int n_in,
                              void* d_out, int out_size) {
    const float* x  = (const float*)d_in[0];     // [65536, 512] f32
    const float* wc = (const float*)d_in[1];     // [512, 32, 9] f32
    float* out = (float*)d_out;                  // [65536, 32] f32

    int Brows = in_sizes[0] / P_I;

    int wtot = P_NCH * P_O * P_CHK;              // 147456
    repack_kernel<<<(wtot + 255) / 256, 256>>>(wc);

    cheby_mma_kernel<<<Brows / P_ROWS, P_THR, SM_TOT>>>(x, out);
}

// round 11
// speedup vs baseline: 2.1132x; 1.6870x over previous
#include <cuda_runtime.h>
#include <cuda_fp16.h>
#include <stdint.h>

// Problem constants
#define F_I     512
#define F_O     32
#define F_NCH   32                 // i-chunks of 16
#define F_WROWS 16                 // rows per warp
#define F_THR   128                // 4 warps -> 64 rows per CTA

// W packed in exact mma A-fragment order:
//   g_Wf[ ((c*8 + ks)*2 + oT)*32 + lane ] = uint4{a0,a1,a2,a3}
//   A[rr][kk] = fp16( W[i = c*16+kk][o = oT*16+rr][j = ks+1] )
__device__ uint4 g_Wf[F_NCH * 8 * 2 * 32];
__device__ float g_bias[F_O];

__device__ __forceinline__ uint32_t pack2(float a, float b) {
    __half2 h = __floats2half2_rn(a, b);
    return *reinterpret_cast<uint32_t*>(&h);
}

__global__ void repack_frag_kernel(const float* __restrict__ w) {
    int idx = blockIdx.x * blockDim.x + threadIdx.x;   // 16384
    if (idx >= F_NCH * 8 * 2 * 32) return;
    int l  = idx & 31;
    int oT = (idx >> 5) & 1;
    int ks = (idx >> 6) & 7;
    int c  = idx >> 9;
    int r  = l >> 2;           // A-frag row within 8 (o low)
    int cf = l & 3;            // k-quad
    int j  = ks + 1;
    int i0 = c * 16 + 2 * cf;  // a0/a1 k positions: i0, i0+1
    int i8 = i0 + 8;           // a2/a3: i8, i8+1
    int oA = oT * 16 + r;
    int oB = oA + 8;
    // W gmem layout: w[(i*32 + o)*9 + j]
    uint4 v;
    v.x = pack2(w[(i0 * F_O + oA) * 9 + j], w[((i0 + 1) * F_O + oA) * 9 + j]);
    v.y = pack2(w[(i0 * F_O + oB) * 9 + j], w[((i0 + 1) * F_O + oB) * 9 + j]);
    v.z = pack2(w[(i8 * F_O + oA) * 9 + j], w[((i8 + 1) * F_O + oA) * 9 + j]);
    v.w = pack2(w[(i8 * F_O + oB) * 9 + j], w[((i8 + 1) * F_O + oB) * 9 + j]);
    g_Wf[idx] = v;
}

// Parallel bias (j=0 fold): 256 threads, smem reduce
__global__ void bias_kernel(const float* __restrict__ w) {
    __shared__ float red[256];
    int t = threadIdx.x;
    int o = t & 31, g = t >> 5;
    float s = 0.0f;
#pragma unroll 8
    for (int i = g; i < F_I; i += 8) s += w[(i * F_O + o) * 9];
    red[t] = s;
    __syncthreads();
    if (t < 32) {
        float tot = 0.0f;
#pragma unroll
        for (int q = 0; q < 8; ++q) tot += red[q * 32 + t];
        g_bias[t] = tot;
    }
}

__device__ __forceinline__ void mma16816(float (&d)[4], const uint32_t (&a)[4],
                                         uint32_t b0, uint32_t b1) {
    asm volatile(
        "mma.sync.aligned.m16n8k16.row.col.f32.f16.f16.f32 "
        "{%0,%1,%2,%3}, {%4,%5,%6,%7}, {%8,%9}, {%0,%1,%2,%3};"
        : "+f"(d[0]), "+f"(d[1]), "+f"(d[2]), "+f"(d[3])
        : "r"(a[0]), "r"(a[1]), "r"(a[2]), "r"(a[3]), "r"(b0), "r"(b1));
}
// tanh(x) = 1 - 2/(exp2(2x*log2e)+1)
__device__ __forceinline__ float ftanh(float x) {
    float p;
    asm("ex2.approx.f32 %0, %1;" : "=f"(p) : "f"(x * 2.8853900817779268f));
    float r;
    asm("rcp.approx.f32 %0, %1;" : "=f"(r) : "f"(p + 1.0f));
    return fmaf(-2.0f, r, 1.0f);
}

__global__ __launch_bounds__(F_THR, 5)
void cheby_frag_kernel(const float* __restrict__ x, float* __restrict__ out) {
    const int t    = threadIdx.x;
    const int lane = t & 31;
    const int w    = t >> 5;
    const int rowBase = blockIdx.x * (4 * F_WROWS) + w * F_WROWS;
    const int r  = lane >> 2;     // B-frag row-in-tile / A-frag o-low
    const int cf = lane & 3;

    // x pointers: tile 0 row = rowBase + r, tile 1 row = rowBase + 8 + r
    const float* xp0 = x + (size_t)(rowBase + r) * F_I + 2 * cf;
    const float* xp1 = x + (size_t)(rowBase + 8 + r) * F_I + 2 * cf;

    float acc[2][2][4];           // [oT][tile][frag]
#pragma unroll
    for (int a = 0; a < 2; ++a)
#pragma unroll
        for (int b = 0; b < 2; ++b)
#pragma unroll
            for (int q = 0; q < 4; ++q) acc[a][b][q] = 0.0f;

    const uint4* wp0 = g_Wf + lane;

    for (int c = 0; c < F_NCH; ++c) {
        const int off = c * 16;
        // lane's 4 i's per tile: {2cf, 2cf+1} and {8+2cf, 8+2cf+1}
        float2 vA0 = *reinterpret_cast<const float2*>(xp0 + off);
        float2 vB0 = *reinterpret_cast<const float2*>(xp0 + off + 8);
        float2 vA1 = *reinterpret_cast<const float2*>(xp1 + off);
        float2 vB1 = *reinterpret_cast<const float2*>(xp1 + off + 8);
        if (c + 1 < F_NCH) {      // L2 prefetch next chunk's x
            asm volatile("prefetch.global.L2 [%0];" :: "l"(xp0 + off + 16));
            asm volatile("prefetch.global.L2 [%0];" :: "l"(xp1 + off + 16));
        }

        // recurrence states: [tile][X], X: 0=iA,1=iB,2=iC,3=iD
        float x2[2][4], up[2][4], uc[2][4];
        {
            float xin[2][4] = {{vA0.x, vA0.y, vB0.x, vB0.y},
                               {vA1.x, vA1.y, vB1.x, vB1.y}};
#pragma unroll
            for (int tl = 0; tl < 2; ++tl)
#pragma unroll
                for (int q = 0; q < 4; ++q) {
                    float th = ftanh(xin[tl][q]);
                    x2[tl][q] = th + th;
                    up[tl][q] = 1.0f;       // U0 (folded into bias)
                    uc[tl][q] = x2[tl][q];  // U1
                }
        }

        const uint4* wp = wp0 + c * (8 * 2 * 32);
#pragma unroll
        for (int ks = 0; ks < 8; ++ks) {
            uint4 w0 = wp[0];
            uint4 w1 = wp[32];
            wp += 64;
            uint32_t a0[4] = {w0.x, w0.y, w0.z, w0.w};
            uint32_t a1[4] = {w1.x, w1.y, w1.z, w1.w};
#pragma unroll
            for (int tl = 0; tl < 2; ++tl) {
                uint32_t b0 = pack2(uc[tl][0], uc[tl][1]);
                uint32_t b1 = pack2(uc[tl][2], uc[tl][3]);
                mma16816(acc[0][tl], a0, b0, b1);
                mma16816(acc[1][tl], a1, b0, b1);
            }
            if (ks < 7) {
#pragma unroll
                for (int tl = 0; tl < 2; ++tl)
#pragma unroll
                    for (int q = 0; q < 4; ++q) {
                        float un = fmaf(x2[tl][q], uc[tl][q], -up[tl][q]);
                        up[tl][q] = uc[tl][q];
                        uc[tl][q] = un;
                    }
            }
        }
    }

    // ---- epilogue: C frag (m = o = l>>2 (+8), n = batch row = 2cf (+1)) ----
    float b0a = g_bias[r],      b0b = g_bias[r + 8];        // oT=0
    float b1a = g_bias[16 + r], b1b = g_bias[16 + r + 8];   // oT=1
#pragma unroll
    for (int tl = 0; tl < 2; ++tl) {
        int rA = rowBase + 8 * tl + 2 * cf;
        float* pA = out + (size_t)rA * F_O;
        float* pB = pA + F_O;
        pA[r]          = acc[0][tl][0] + b0a;
        pB[r]          = acc[0][tl][1] + b0a;
        pA[r + 8]      = acc[0][tl][2] + b0b;
        pB[r + 8]      = acc[0][tl][3] + b0b;
        pA[16 + r]     = acc[1][tl][0] + b1a;
        pB[16 + r]     = acc[1][tl][1] + b1a;
        pA[16 + r + 8] = acc[1][tl][2] + b1b;
        pB[16 + r + 8] = acc[1][tl][3] + b1b;
    }
}

extern "C" void kernel_launch(void* const* d_in, const int* in_sizes, int n_in,
                              void* d_out, int out_size) {
    const float* x  = (const float*)d_in[0];     // [65536, 512] f32
    const float* wc = (const float*)d_in[1];     // [512, 32, 9] f32
    float* out = (float*)d_out;                  // [65536, 32] f32

    int Brows = in_sizes[0] / F_I;               // 65536

    repack_frag_kernel<<<(F_NCH * 8 * 2 * 32 + 255) / 256, 256>>>(wc);
    bias_kernel<<<1, 256>>>(wc);

    cheby_frag_kernel<<<Brows / 64, F_THR>>>(x, out);
}